// round 2
// baseline (speedup 1.0000x reference)
#include <cuda_runtime.h>
#include <cstring>
#include <cmath>

#define S_NUM 50
#define CH    64
#define TT    200
#define VV    25
#define BB    16
#define HID   128
#define GDIM  512
#define KDIM  2144
#define MTOT  20000
#define MPAD  20096   // 157 * 128

// ---- scratch (static device globals; no allocation) ----
__device__ float  g_F [(size_t)MPAD * KDIM];   // logsig features, row-major [M][K]
__device__ float  g_XP[(size_t)MPAD * GDIM];   // x_proj + biases, row-major [M][512]
__device__ float2 g_Wt[64 * GDIM];             // W_hh transposed: [k/2][gate] as float2

// ============================================================
// Kernel 1: segment log-signature features
// F[m] = [lvl1(64) | levy(2016) | start(64)],  m = n*50 + s
// ============================================================
__global__ void logsig_kernel(const float* __restrict__ x) {
    const int m = blockIdx.x;        // 0..19999
    const int n = m / S_NUM, s = m - n * S_NUM;
    const int b = n / VV,   v = n - b * VV;
    const int c = threadIdx.x;       // 64 threads, one channel each

    __shared__ float sp[4][CH];

    const float* xp = x + ((size_t)(b * CH + c) * TT + 4 * s) * VV + v;
    float p0 = xp[0];
    float p1 = xp[VV];
    float p2 = xp[2 * VV];
    float p3 = xp[3 * VV];
    sp[0][c] = p0; sp[1][c] = p1; sp[2][c] = p2; sp[3][c] = p3;

    float* Frow = g_F + (size_t)m * KDIM;
    Frow[c]        = p3 - p0;  // lvl1
    Frow[2080 + c] = p0;       // start
    __syncthreads();

    // Levy area: since dev[t=0] = 0, only t=1,2 contribute.
    const int i = c;
    const float d1i = p1 - p0, d2i = p2 - p0;
    const float i1i = p2 - p1, i2i = p3 - p2;
    const int base = 64 + i * 63 - (i * (i - 1)) / 2;
    for (int j = i + 1; j < CH; ++j) {
        float q0 = sp[0][j], q1 = sp[1][j], q2 = sp[2][j], q3 = sp[3][j];
        float d1j = q1 - q0, d2j = q2 - q0;
        float i1j = q2 - q1, i2j = q3 - q2;
        float a = 0.5f * ((d1i * i1j - d1j * i1i) + (d2i * i2j - d2j * i2i));
        Frow[base + (j - i - 1)] = a;
    }
}

// ============================================================
// Kernel 2: transpose W_hh -> g_Wt[k2][g] = (W[g][2k2], W[g][2k2+1])
// ============================================================
__global__ void wt_kernel(const float* __restrict__ Whh) {
    const int k2 = blockIdx.x;     // 0..63
    const int g  = threadIdx.x;    // 0..511
    g_Wt[k2 * GDIM + g] = make_float2(Whh[g * HID + 2 * k2],
                                      Whh[g * HID + 2 * k2 + 1]);
}

// ============================================================
// Kernel 3: GEMM  XP[M][512] = F[M][2144] @ Wih^T + b_ih + b_hh
// 128x128 block tile, BK=16, 256 threads, 8x8 per thread,
// fma.rn.f32x2 packed over m-pairs. Double-buffered smem.
// ============================================================
__global__ void __launch_bounds__(256) gemm_kernel(const float* __restrict__ Wih,
                                                   const float* __restrict__ bih,
                                                   const float* __restrict__ bhh) {
    __shared__ float As[2][16][132];   // [k][m], pad to kill bank conflicts
    __shared__ float Bs[2][16][132];   // [k][n]

    const int tid = threadIdx.x;
    const int tx = tid & 15, ty = tid >> 4;
    const int m0 = blockIdx.y * 128;
    const int n0 = blockIdx.x * 128;

    const int arow = tid >> 2, akq = (tid & 3) << 2;   // A fill: (row, 4k)
    const int bn   = tid >> 1, bkq = (tid & 1) << 3;   // B fill: (n, 8k)

    float4 ra0, ra1, rb0, rb1;
    auto LOAD = [&](int kt) {
        const int k0 = kt << 4;
        ra0 = *(const float4*)(g_F + (size_t)(m0 + arow)      * KDIM + k0 + akq);
        ra1 = *(const float4*)(g_F + (size_t)(m0 + 64 + arow) * KDIM + k0 + akq);
        rb0 = *(const float4*)(Wih + (size_t)(n0 + bn) * KDIM + k0 + bkq);
        rb1 = *(const float4*)(Wih + (size_t)(n0 + bn) * KDIM + k0 + bkq + 4);
    };

    unsigned long long acc[4][8];
    #pragma unroll
    for (int u = 0; u < 4; ++u)
        #pragma unroll
        for (int j = 0; j < 8; ++j) acc[u][j] = 0ull;

    LOAD(0);
    int buf = 0;
    for (int kt = 0; kt < KDIM / 16; ++kt) {
        // stage regs -> smem (A transposed to [k][m], B to [k][n])
        As[buf][akq + 0][arow] = ra0.x; As[buf][akq + 1][arow] = ra0.y;
        As[buf][akq + 2][arow] = ra0.z; As[buf][akq + 3][arow] = ra0.w;
        As[buf][akq + 0][arow + 64] = ra1.x; As[buf][akq + 1][arow + 64] = ra1.y;
        As[buf][akq + 2][arow + 64] = ra1.z; As[buf][akq + 3][arow + 64] = ra1.w;
        Bs[buf][bkq + 0][bn] = rb0.x; Bs[buf][bkq + 1][bn] = rb0.y;
        Bs[buf][bkq + 2][bn] = rb0.z; Bs[buf][bkq + 3][bn] = rb0.w;
        Bs[buf][bkq + 4][bn] = rb1.x; Bs[buf][bkq + 5][bn] = rb1.y;
        Bs[buf][bkq + 6][bn] = rb1.z; Bs[buf][bkq + 7][bn] = rb1.w;
        __syncthreads();

        if (kt + 1 < KDIM / 16) LOAD(kt + 1);

        #pragma unroll
        for (int kk = 0; kk < 16; ++kk) {
            unsigned long long a2[4];
            #pragma unroll
            for (int u = 0; u < 4; ++u) {
                float2 av = *(const float2*)&As[buf][kk][(ty << 3) + (u << 1)];
                memcpy(&a2[u], &av, 8);
            }
            float bv[8];
            #pragma unroll
            for (int j = 0; j < 4; ++j) {
                bv[j]     = Bs[buf][kk][(tx << 2) + j];
                bv[4 + j] = Bs[buf][kk][64 + (tx << 2) + j];
            }
            #pragma unroll
            for (int j = 0; j < 8; ++j) {
                unsigned long long b2;
                asm("mov.b64 %0, {%1, %1};" : "=l"(b2) : "f"(bv[j]));
                #pragma unroll
                for (int u = 0; u < 4; ++u)
                    asm("fma.rn.f32x2 %0, %1, %2, %0;"
                        : "+l"(acc[u][j]) : "l"(a2[u]), "l"(b2));
            }
        }
        buf ^= 1;
    }

    // epilogue: add biases, store
    #pragma unroll
    for (int j = 0; j < 8; ++j) {
        const int nn = n0 + ((j < 4) ? ((tx << 2) + j) : (64 + (tx << 2) + (j - 4)));
        const float bias = bih[nn] + bhh[nn];
        #pragma unroll
        for (int u = 0; u < 4; ++u) {
            float2 vv; memcpy(&vv, &acc[u][j], 8);
            const int m = m0 + (ty << 3) + (u << 1);
            g_XP[(size_t)m * GDIM + nn]       = vv.x + bias;
            g_XP[(size_t)(m + 1) * GDIM + nn] = vv.y + bias;
        }
    }
}

// ============================================================
// Kernel 4: LSTM, 4 sequences per CTA, 100 CTAs, 512 threads.
// Each thread owns one gate g for all 4 sequences. W_hh streamed
// from L2 (transposed, coalesced). h/c updated in smem/regs.
// Writes output directly in (B, HID, S, V) layout.
// ============================================================
__device__ __forceinline__ float sigm(float x) { return 1.0f / (1.0f + expf(-x)); }

__global__ void __launch_bounds__(512) lstm_kernel(float* __restrict__ out) {
    __shared__ float hsm[4][HID];
    __shared__ float gsm[4][GDIM];

    const int tid = threadIdx.x;
    const int n0 = blockIdx.x << 2;          // 4 sequences per CTA, 100*4 = 400 exact
    const int g = tid;
    const int r_up = tid >> 7, hid = tid & 127;

    hsm[r_up][hid] = 0.0f;
    float c_reg = 0.0f;

    const int nu = n0 + r_up;
    const int bq = nu / VV, vq = nu - bq * VV;
    float* outp = out + ((size_t)(bq * HID + hid) * S_NUM) * VV + vq;

    __syncthreads();

    for (int s = 0; s < S_NUM; ++s) {
        float acc0 = g_XP[((size_t)(n0 + 0) * S_NUM + s) * GDIM + g];
        float acc1 = g_XP[((size_t)(n0 + 1) * S_NUM + s) * GDIM + g];
        float acc2 = g_XP[((size_t)(n0 + 2) * S_NUM + s) * GDIM + g];
        float acc3 = g_XP[((size_t)(n0 + 3) * S_NUM + s) * GDIM + g];

        const float2* h0p = (const float2*)hsm[0];
        const float2* h1p = (const float2*)hsm[1];
        const float2* h2p = (const float2*)hsm[2];
        const float2* h3p = (const float2*)hsm[3];

        #pragma unroll 8
        for (int k2 = 0; k2 < 64; ++k2) {
            float2 w = __ldg(&g_Wt[(k2 << 9) + g]);
            float2 h0 = h0p[k2]; acc0 = fmaf(w.y, h0.y, fmaf(w.x, h0.x, acc0));
            float2 h1 = h1p[k2]; acc1 = fmaf(w.y, h1.y, fmaf(w.x, h1.x, acc1));
            float2 h2 = h2p[k2]; acc2 = fmaf(w.y, h2.y, fmaf(w.x, h2.x, acc2));
            float2 h3 = h3p[k2]; acc3 = fmaf(w.y, h3.y, fmaf(w.x, h3.x, acc3));
        }
        gsm[0][g] = acc0; gsm[1][g] = acc1; gsm[2][g] = acc2; gsm[3][g] = acc3;
        __syncthreads();

        // update: each thread handles one (seq r_up, hidden hid)
        const float iv = gsm[r_up][hid];
        const float fv = gsm[r_up][128 + hid];
        const float gv = gsm[r_up][256 + hid];
        const float ov = gsm[r_up][384 + hid];
        c_reg = sigm(fv) * c_reg + sigm(iv) * tanhf(gv);
        const float hv = sigm(ov) * tanhf(c_reg);
        hsm[r_up][hid] = hv;
        outp[s * VV] = hv;
        __syncthreads();
    }
}

// ============================================================
extern "C" void kernel_launch(void* const* d_in, const int* in_sizes, int n_in,
                              void* d_out, int out_size) {
    const float* x   = (const float*)d_in[0];
    const float* Wih = (const float*)d_in[1];
    const float* Whh = (const float*)d_in[2];
    const float* bih = (const float*)d_in[3];
    const float* bhh = (const float*)d_in[4];
    float* out = (float*)d_out;

    logsig_kernel<<<MTOT, CH>>>(x);
    wt_kernel<<<64, GDIM>>>(Whh);
    gemm_kernel<<<dim3(GDIM / 128, MPAD / 128), 256>>>(Wih, bih, bhh);
    lstm_kernel<<<100, 512>>>(out);
}

// round 7
// speedup vs baseline: 1.1371x; 1.1371x over previous
#include <cuda_runtime.h>
#include <cuda_fp16.h>
#include <cstring>
#include <cmath>
#include <cstdint>

#define S_NUM 50
#define CH    64
#define TT    200
#define VV    25
#define HID   128
#define GDIM  512
#define KDIM  2144
#define KPAD  2176      // 68 * 32
#define NSTAGE 68
#define MTOT  20000
#define MPAD  20096     // 157 * 128

// ---- scratch (static device globals; zero-initialized, no allocation) ----
__device__ __half g_Fhi[(size_t)MPAD * KPAD];
__device__ __half g_Flo[(size_t)MPAD * KPAD];
__device__ __half g_Whi[(size_t)GDIM * KPAD];
__device__ __half g_Wlo[(size_t)GDIM * KPAD];
__device__ float  g_XP[(size_t)MPAD * GDIM];       // x_proj + biases
__device__ float4 g_Wt4[32 * GDIM];                // W_hh: [k/4][gate] -> 4 k's
__device__ float  g_bias[GDIM];
__device__ float  g_stage[(size_t)400 * S_NUM * HID];

// ================= helpers =================
__device__ __forceinline__ uint32_t s2u(const void* p) {
    uint32_t a;
    asm("{ .reg .u64 t; cvta.to.shared.u64 t, %1; cvt.u32.u64 %0, t; }" : "=r"(a) : "l"(p));
    return a;
}
__device__ __forceinline__ void cpasync16(uint32_t s, const void* g) {
    asm volatile("cp.async.cg.shared.global [%0], [%1], 16;" :: "r"(s), "l"(g) : "memory");
}
__device__ __forceinline__ void cp_commit() {
    asm volatile("cp.async.commit_group;" ::: "memory");
}
#define LDSM4(r0, r1, r2, r3, addr) \
    asm volatile("ldmatrix.sync.aligned.m8n8.x4.shared.b16 {%0,%1,%2,%3}, [%4];" \
                 : "=r"(r0), "=r"(r1), "=r"(r2), "=r"(r3) : "r"(addr))
#define HMMA(d, a, b) \
    asm volatile("mma.sync.aligned.m16n8k16.row.col.f32.f16.f16.f32 " \
                 "{%0,%1,%2,%3}, {%4,%5,%6,%7}, {%8,%9}, {%0,%1,%2,%3};" \
                 : "+f"((d)[0]), "+f"((d)[1]), "+f"((d)[2]), "+f"((d)[3]) \
                 : "r"((a)[0]), "r"((a)[1]), "r"((a)[2]), "r"((a)[3]), \
                   "r"((b)[0]), "r"((b)[1]))

__device__ __forceinline__ unsigned long long pack2(float a, float b) {
    unsigned long long r; asm("mov.b64 %0, {%1, %2};" : "=l"(r) : "f"(a), "f"(b)); return r;
}
__device__ __forceinline__ void unpack2(unsigned long long v, float& a, float& b) {
    asm("mov.b64 {%0, %1}, %2;" : "=f"(a), "=f"(b) : "l"(v));
}
__device__ __forceinline__ void fma2(unsigned long long& acc, unsigned long long a,
                                     unsigned long long b) {
    asm("fma.rn.f32x2 %0, %1, %2, %0;" : "+l"(acc) : "l"(a), "l"(b));
}

// ============================================================
// Kernel 1: segment log-signature -> fp16 hi/lo, smem staged
// F[m] = [lvl1(64) | levy(2016) | start(64) | pad(32)]
// ============================================================
__device__ __forceinline__ void puth(__half* fh, __half* fl, int i, float v) {
    __half h = __float2half(v);
    fh[i] = h;
    fl[i] = __float2half(v - __half2float(h));
}

__global__ void logsig_kernel(const float* __restrict__ x) {
    const int m = blockIdx.x;
    const int n = m / S_NUM, s = m - n * S_NUM;
    const int b = n / VV,   v = n - b * VV;
    const int c = threadIdx.x;   // 64 threads

    __shared__ float sp[4][CH];
    __shared__ __align__(16) __half fh[KPAD];
    __shared__ __align__(16) __half fl[KPAD];

    const float* xp = x + ((size_t)(b * CH + c) * TT + 4 * s) * VV + v;
    float p0 = xp[0], p1 = xp[VV], p2 = xp[2 * VV], p3 = xp[3 * VV];
    sp[0][c] = p0; sp[1][c] = p1; sp[2][c] = p2; sp[3][c] = p3;

    puth(fh, fl, c, p3 - p0);          // lvl1
    puth(fh, fl, 2080 + c, p0);        // start
    if (c < 32) {                      // K padding
        fh[2144 + c] = __float2half(0.f);
        fl[2144 + c] = __float2half(0.f);
    }
    __syncthreads();

    const int i = c;
    const float d1i = p1 - p0, d2i = p2 - p0;
    const float i1i = p2 - p1, i2i = p3 - p2;
    const int base = 64 + i * 63 - (i * (i - 1)) / 2;
    for (int j = i + 1; j < CH; ++j) {
        float q0 = sp[0][j], q1 = sp[1][j], q2 = sp[2][j], q3 = sp[3][j];
        float d1j = q1 - q0, d2j = q2 - q0;
        float i1j = q2 - q1, i2j = q3 - q2;
        float a = 0.5f * ((d1i * i1j - d1j * i1i) + (d2i * i2j - d2j * i2i));
        puth(fh, fl, base + (j - i - 1), a);
    }
    __syncthreads();

    // coalesced copy out: KPAD*2B = 272 x 16B per array
    const uint4* s4h = (const uint4*)fh;
    const uint4* s4l = (const uint4*)fl;
    uint4* dh = (uint4*)(g_Fhi + (size_t)m * KPAD);
    uint4* dl = (uint4*)(g_Flo + (size_t)m * KPAD);
    for (int t = c; t < 272; t += 64) { dh[t] = s4h[t]; dl[t] = s4l[t]; }
}

// ============================================================
// Kernel 2: weight prep (Wih -> fp16 hi/lo padded; Whh -> 4-k packs; bias)
// ============================================================
__global__ void prep_kernel(const float* __restrict__ Wih, const float* __restrict__ Whh,
                            const float* __restrict__ bih, const float* __restrict__ bhh) {
    const int gate = blockIdx.x;   // 512
    for (int k = threadIdx.x; k < KPAD; k += 128) {
        float vv = (k < KDIM) ? Wih[(size_t)gate * KDIM + k] : 0.f;
        __half h = __float2half(vv);
        g_Whi[(size_t)gate * KPAD + k] = h;
        g_Wlo[(size_t)gate * KPAD + k] = __float2half(vv - __half2float(h));
    }
    if (threadIdx.x < 128) {
        int k = threadIdx.x;
        ((float*)g_Wt4)[(((k >> 2) * GDIM) + gate) * 4 + (k & 3)] = Whh[gate * HID + k];
    }
    if (threadIdx.x == 0) g_bias[gate] = bih[gate] + bhh[gate];
}

// ============================================================
// Kernel 3: HMMA GEMM  XP = F @ Wih^T  (fp16 hi/lo split, fp32 acc)
// CTA 128x128, 8 warps (4m x 2n), warp 32x64, BK=32, cp.async double buffer.
// smem per buffer: [Ahi|Alo|Bhi|Blo], each 128 rows x 40 halves (pad) = 10240B.
// ============================================================
#define SSTRIDE 40               // halves per row (32 data + 8 pad)
#define TILEB   10240u           // 128 * 40 * 2
#define BUFB    (4u * TILEB)     // 40960

__global__ void __launch_bounds__(256) gemm_mma() {
    extern __shared__ __align__(16) char dynsm[];
    const uint32_t sb = s2u(dynsm);

    const int tid  = threadIdx.x;
    const int lane = tid & 31;
    const int wid  = tid >> 5;
    const int wm   = wid & 3;       // m warp: 32 rows each
    const int wn   = wid >> 2;      // n warp: 64 cols each
    const int m0 = blockIdx.y * 128;
    const int n0 = blockIdx.x * 128;

    float d[2][8][4];
    #pragma unroll
    for (int mt = 0; mt < 2; ++mt)
        #pragma unroll
        for (int nt = 0; nt < 8; ++nt)
            #pragma unroll
            for (int q = 0; q < 4; ++q) d[mt][nt][q] = 0.f;

    auto G2S = [&](int st, int bsel) {
        const int kc = st * 32;
        const uint32_t ab = sb + (uint32_t)bsel * BUFB;
        #pragma unroll
        for (int i = 0; i < 2; ++i) {
            const int idx = tid + i * 256;
            const int row = idx >> 2, q = idx & 3;
            const uint32_t dof = ab + (uint32_t)(row * (SSTRIDE * 2) + q * 16);
            const size_t ga = (size_t)(m0 + row) * KPAD + kc + q * 8;
            const size_t gb = (size_t)(n0 + row) * KPAD + kc + q * 8;
            cpasync16(dof,              g_Fhi + ga);
            cpasync16(dof + TILEB,      g_Flo + ga);
            cpasync16(dof + 2 * TILEB,  g_Whi + gb);
            cpasync16(dof + 3 * TILEB,  g_Wlo + gb);
        }
        cp_commit();
    };

    G2S(0, 0);
    int b = 0;
    for (int s = 0; s < NSTAGE; ++s) {
        if (s + 1 < NSTAGE) {
            G2S(s + 1, b ^ 1);
            asm volatile("cp.async.wait_group 1;" ::: "memory");
        } else {
            asm volatile("cp.async.wait_group 0;" ::: "memory");
        }
        __syncthreads();

        const uint32_t base = sb + (uint32_t)b * BUFB;
        #pragma unroll
        for (int kk = 0; kk < 32; kk += 16) {
            uint32_t ah[2][4], al[2][4];
            #pragma unroll
            for (int mt = 0; mt < 2; ++mt) {
                const uint32_t r = base +
                    (uint32_t)((wm * 32 + mt * 16 + (lane & 15)) * (SSTRIDE * 2) +
                               (kk + (lane >> 4) * 8) * 2);
                LDSM4(ah[mt][0], ah[mt][1], ah[mt][2], ah[mt][3], r);
                LDSM4(al[mt][0], al[mt][1], al[mt][2], al[mt][3], r + TILEB);
            }
            uint32_t bh[8][2], bl[8][2];
            #pragma unroll
            for (int nt4 = 0; nt4 < 4; ++nt4) {
                const int rowb = wn * 64 + nt4 * 16 + ((lane & 7) | ((lane & 16) >> 1));
                const uint32_t r = base + 2 * TILEB +
                    (uint32_t)(rowb * (SSTRIDE * 2) +
                               (kk + ((lane >> 3) & 1) * 8) * 2);
                uint32_t t0, t1, t2, t3;
                LDSM4(t0, t1, t2, t3, r);
                bh[nt4 * 2][0] = t0; bh[nt4 * 2][1] = t1;
                bh[nt4 * 2 + 1][0] = t2; bh[nt4 * 2 + 1][1] = t3;
                LDSM4(t0, t1, t2, t3, r + TILEB);
                bl[nt4 * 2][0] = t0; bl[nt4 * 2][1] = t1;
                bl[nt4 * 2 + 1][0] = t2; bl[nt4 * 2 + 1][1] = t3;
            }
            #pragma unroll
            for (int mt = 0; mt < 2; ++mt)
                #pragma unroll
                for (int nt = 0; nt < 8; ++nt) {
                    HMMA(d[mt][nt], ah[mt], bh[nt]);
                    HMMA(d[mt][nt], ah[mt], bl[nt]);
                    HMMA(d[mt][nt], al[mt], bh[nt]);
                }
        }
        __syncthreads();
        b ^= 1;
    }

    // epilogue: add biases, store to g_XP
    #pragma unroll
    for (int nt = 0; nt < 8; ++nt) {
        const int nb = n0 + wn * 64 + nt * 8 + (lane & 3) * 2;
        const float b0v = g_bias[nb], b1v = g_bias[nb + 1];
        #pragma unroll
        for (int mt = 0; mt < 2; ++mt) {
            const int mrow = m0 + wm * 32 + mt * 16 + (lane >> 2);
            float2 v0 = make_float2(d[mt][nt][0] + b0v, d[mt][nt][1] + b1v);
            float2 v1 = make_float2(d[mt][nt][2] + b0v, d[mt][nt][3] + b1v);
            *(float2*)(g_XP + (size_t)mrow * GDIM + nb)       = v0;
            *(float2*)(g_XP + (size_t)(mrow + 8) * GDIM + nb) = v1;
        }
    }
}

// ============================================================
// Kernel 4: LSTM. 4 seqs/CTA, 100 CTAs, 512 threads.
// f32x2-packed FMAs over seq pairs; gates 0-255 W in smem, 256-511 from L2.
// ============================================================
__device__ __forceinline__ float sigm(float x) { return 1.0f / (1.0f + __expf(-x)); }

#define LSTM_BODY(WV)                                                            \
    {                                                                            \
        const float4 w = (WV);                                                   \
        ulonglong2 h;                                                            \
        unsigned long long wb;                                                   \
        h = hp[(k4 << 2) + 0]; wb = pack2(w.x, w.x);                             \
        fma2(acc01, wb, h.x); fma2(acc23, wb, h.y);                              \
        h = hp[(k4 << 2) + 1]; wb = pack2(w.y, w.y);                             \
        fma2(acc01, wb, h.x); fma2(acc23, wb, h.y);                              \
        h = hp[(k4 << 2) + 2]; wb = pack2(w.z, w.z);                             \
        fma2(acc01, wb, h.x); fma2(acc23, wb, h.y);                              \
        h = hp[(k4 << 2) + 3]; wb = pack2(w.w, w.w);                             \
        fma2(acc01, wb, h.x); fma2(acc23, wb, h.y);                              \
    }

__global__ void __launch_bounds__(512) lstm_f2() {
    extern __shared__ char dynsm2[];
    float4* Wsm  = (float4*)dynsm2;                    // [32][256] gates 0..255, 128KB
    float*  hsm  = (float*)(dynsm2 + 131072);          // [128 k][4 seq], 2KB
    float*  gsm  = (float*)(dynsm2 + 131072 + 2048);   // [4][512], 8KB

    const int tid = threadIdx.x;
    const int g = tid;
    const int n0 = blockIdx.x << 2;
    const int r_up = tid >> 7, hid = tid & 127;

    for (int i = tid; i < 32 * 256; i += 512) {
        const int k4 = i >> 8, gg = i & 255;
        Wsm[i] = g_Wt4[(k4 << 9) + gg];
    }
    if (tid < 128) ((float4*)hsm)[tid] = make_float4(0.f, 0.f, 0.f, 0.f);
    float c_reg = 0.f;
    __syncthreads();

    const ulonglong2* hp = (const ulonglong2*)hsm;
    const float* xpb = g_XP + (size_t)n0 * S_NUM * GDIM + g;

    for (int s = 0; s < S_NUM; ++s) {
        const float* xp = xpb + (size_t)s * GDIM;
        unsigned long long acc01 = pack2(xp[0], xp[S_NUM * GDIM]);
        unsigned long long acc23 = pack2(xp[2 * S_NUM * GDIM], xp[3 * S_NUM * GDIM]);

        if (g < 256) {
            #pragma unroll 8
            for (int k4 = 0; k4 < 32; ++k4) LSTM_BODY(Wsm[(k4 << 8) + g]);
        } else {
            #pragma unroll 8
            for (int k4 = 0; k4 < 32; ++k4) LSTM_BODY(__ldg(&g_Wt4[(k4 << 9) + g]));
        }
        float g0, g1, g2, g3;
        unpack2(acc01, g0, g1);
        unpack2(acc23, g2, g3);
        gsm[g] = g0; gsm[512 + g] = g1; gsm[1024 + g] = g2; gsm[1536 + g] = g3;
        __syncthreads();

        const float iv = gsm[(r_up << 9) + hid];
        const float fv = gsm[(r_up << 9) + 128 + hid];
        const float gv = gsm[(r_up << 9) + 256 + hid];
        const float ov = gsm[(r_up << 9) + 384 + hid];
        c_reg = sigm(fv) * c_reg + sigm(iv) * tanhf(gv);
        const float hv = sigm(ov) * tanhf(c_reg);
        hsm[(hid << 2) + r_up] = hv;
        g_stage[((size_t)(n0 + r_up) * S_NUM + s) * HID + hid] = hv;
        __syncthreads();
    }
}

// ============================================================
// Kernel 5: output transpose stage[n][s][hid] -> out[b][hid][s][v]
// ============================================================
__global__ void outtrans_kernel(float* __restrict__ out) {
    __shared__ float t[VV][129];
    const int bs = blockIdx.x;            // 16*50
    const int b = bs / S_NUM, s = bs - b * S_NUM;
    const int tid = threadIdx.x;          // 128
    for (int v = 0; v < VV; ++v)
        t[v][tid] = g_stage[((size_t)(b * VV + v) * S_NUM + s) * HID + tid];
    __syncthreads();
    for (int idx = tid; idx < HID * VV; idx += 128) {
        const int hid = idx / VV, v = idx - hid * VV;
        out[((size_t)(b * HID + hid) * S_NUM + s) * VV + v] = t[v][hid];
    }
}

// ============================================================
extern "C" void kernel_launch(void* const* d_in, const int* in_sizes, int n_in,
                              void* d_out, int out_size) {
    const float* x   = (const float*)d_in[0];
    const float* Wih = (const float*)d_in[1];
    const float* Whh = (const float*)d_in[2];
    const float* bih = (const float*)d_in[3];
    const float* bhh = (const float*)d_in[4];
    float* out = (float*)d_out;

    cudaFuncSetAttribute(gemm_mma, cudaFuncAttributeMaxDynamicSharedMemorySize, 81920);
    cudaFuncSetAttribute(lstm_f2,  cudaFuncAttributeMaxDynamicSharedMemorySize, 141312);

    logsig_kernel<<<MTOT, CH>>>(x);
    prep_kernel<<<GDIM, 128>>>(Wih, Whh, bih, bhh);
    gemm_mma<<<dim3(GDIM / 128, MPAD / 128), 256, 81920>>>();
    lstm_f2<<<100, 512, 141312>>>();
    outtrans_kernel<<<16 * S_NUM, 128>>>(out);
}